// round 11
// baseline (speedup 1.0000x reference)
#include <cuda_runtime.h>
#include <cuda_bf16.h>
#include <cstdint>

#define N_TOK 49
#define C_DIM 96
#define RS 80          // row stride bytes (64B data + 16B pad)
#define QHI 0
#define QLO 5120
#define KHI 10240
#define KLO 15360
#define VHI 20480
#define VLO 25600
#define SMEM_BYTES 30720

__device__ float4 g_bias4[3 * 4 * 7 * 32];  // C-fragment-ordered bias table

// ---------------------------------------------------------------------------
__device__ __forceinline__ uint32_t smem_u32(const void* p) {
    uint32_t a;
    asm("{ .reg .u64 t; cvta.to.shared.u64 t, %1; cvt.u32.u64 %0, t; }" : "=r"(a) : "l"(p));
    return a;
}
__device__ __forceinline__ void ldsm4(uint32_t r[4], uint32_t addr) {
    asm volatile("ldmatrix.sync.aligned.m8n8.x4.shared.b16 {%0,%1,%2,%3}, [%4];"
                 : "=r"(r[0]), "=r"(r[1]), "=r"(r[2]), "=r"(r[3]) : "r"(addr));
}
__device__ __forceinline__ void ldsm4t(uint32_t r[4], uint32_t addr) {
    asm volatile("ldmatrix.sync.aligned.m8n8.x4.trans.shared.b16 {%0,%1,%2,%3}, [%4];"
                 : "=r"(r[0]), "=r"(r[1]), "=r"(r[2]), "=r"(r[3]) : "r"(addr));
}
__device__ __forceinline__ void mma16816(float c[4], const uint32_t a[4],
                                         uint32_t b0, uint32_t b1) {
    asm volatile(
        "mma.sync.aligned.m16n8k16.row.col.f32.bf16.bf16.f32 "
        "{%0,%1,%2,%3}, {%4,%5,%6,%7}, {%8,%9}, {%0,%1,%2,%3};"
        : "+f"(c[0]), "+f"(c[1]), "+f"(c[2]), "+f"(c[3])
        : "r"(a[0]), "r"(a[1]), "r"(a[2]), "r"(a[3]), "r"(b0), "r"(b1));
}
// split (x,y) into packed bf16 hi + bf16 lo (x ~= hi + lo)
__device__ __forceinline__ void cvt2(float x, float y, uint32_t& hi, uint32_t& lo) {
    __nv_bfloat162 h = __floats2bfloat162_rn(x, y);
    float hx = __bfloat162float(__low2bfloat16(h));
    float hy = __bfloat162float(__high2bfloat16(h));
    __nv_bfloat162 l = __floats2bfloat162_rn(x - hx, y - hy);
    hi = *reinterpret_cast<uint32_t*>(&h);
    lo = *reinterpret_cast<uint32_t*>(&l);
}

// ---------------------------------------------------------------------------
// Bias MLP, slice-parallel (8 lanes per position), writing DIRECTLY into the
// C-fragment-ordered table g_bias4 ([h][m16-tile][j][lane]).
// ---------------------------------------------------------------------------
__global__ void bias_kernel(const float* __restrict__ rel_pos,
                            const float* __restrict__ w1,
                            const float* __restrict__ b1,
                            const float* __restrict__ w2,
                            const float* __restrict__ b2) {
    int gid = blockIdx.x * blockDim.x + threadIdx.x;
    if (gid >= 64 * 56 * 8) return;
    const int s = gid & 7;          // hidden-slice index
    const int p = gid >> 3;         // position [0, 3584)
    const int n = p / 56;
    const int m = p - n * 56;

    float a0 = 0.f, a1 = 0.f, a2 = 0.f;
    const bool live = (n < N_TOK) && (m < N_TOK);
    if (live) {
        const int idx = n * N_TOK + m;
        const float r0 = rel_pos[2 * idx + 0];
        const float r1 = rel_pos[2 * idx + 1];
        const int j0 = s * 32;
        #pragma unroll 8
        for (int j = j0; j < j0 + 32; ++j) {
            float hj = fmaf(r0, __ldg(w1 + j), fmaf(r1, __ldg(w1 + 256 + j), __ldg(b1 + j)));
            hj = fmaxf(hj, 0.0f);
            a0 = fmaf(hj, __ldg(w2 + j * 3 + 0), a0);
            a1 = fmaf(hj, __ldg(w2 + j * 3 + 1), a1);
            a2 = fmaf(hj, __ldg(w2 + j * 3 + 2), a2);
        }
    }
    #pragma unroll
    for (int o = 1; o < 8; o <<= 1) {
        a0 += __shfl_xor_sync(0xffffffffu, a0, o);
        a1 += __shfl_xor_sync(0xffffffffu, a1, o);
        a2 += __shfl_xor_sync(0xffffffffu, a2, o);
    }
    if (s == 0) {
        float v0, v1, v2;
        if (m >= N_TOK)      { v0 = v1 = v2 = -1e30f; }
        else if (n >= N_TOK) { v0 = v1 = v2 = 0.0f; }
        else { v0 = a0 + __ldg(b2 + 0); v1 = a1 + __ldg(b2 + 1); v2 = a2 + __ldg(b2 + 2); }
        const int w    = n >> 4;
        const int half = (n >> 3) & 1;
        const int g    = n & 7;
        const int j    = m >> 3;
        const int tig  = (m & 7) >> 1;
        const int comp = m & 1;
        const int lane4 = g * 4 + tig;
        const int fi    = half * 2 + comp;
        float* base = (float*)g_bias4 + fi;
        base[(((0 * 4 + w) * 7 + j) * 32 + lane4) * 4] = v0;
        base[(((1 * 4 + w) * 7 + j) * 32 + lane4) * 4] = v1;
        base[(((2 * 4 + w) * 7 + j) * 32 + lane4) * 4] = v2;
    }
}

// ---------------------------------------------------------------------------
// CTA = (window, head), 64 threads = 2 warps, warp = 32-row M-tile (2 m16).
// k/v fragments ldsm'd ONCE per warp, reused for both m16 tiles (halves the
// B-operand L1 traffic vs the 4-warp M=16 layout).
// ---------------------------------------------------------------------------
__global__ __launch_bounds__(64, 8)
void attn_kernel(const float* __restrict__ q,
                 const float* __restrict__ k,
                 const float* __restrict__ v,
                 float*       __restrict__ out) {
    __shared__ __align__(16) char S[SMEM_BYTES];
    const uint32_t sb = smem_u32(S);

    const int tid  = threadIdx.x;
    const int lane = tid & 31;
    const int warp = tid >> 5;          // 0..1
    const int g    = lane >> 2;
    const int tig  = lane & 3;
    const int POFF = (lane & 7) + 8 * ((lane >> 3) & 1);
    const int CG   = lane >> 4;
    const int h    = blockIdx.y;
    const size_t wbase = (size_t)blockIdx.x * (N_TOK * C_DIM);

    // ---- stage q (scaled), k, v as bf16 hi/lo; zero pad rows 49..63 ----
    {
        const float SC = 0.17677669529663687f;  // 1/sqrt(32)
        #pragma unroll
        for (int it = 0; it < 8; ++it) {
            int i = tid + it * 64;             // 512 = 64 rows x 8 chunks
            int n = i >> 3, c = i & 7;
            uint32_t off = (uint32_t)(n * RS + c * 8);
            uint2 qh = make_uint2(0, 0), ql = qh, kh = qh, kl = qh, vh = qh, vl = qh;
            if (n < N_TOK) {
                size_t ga = wbase + (size_t)n * C_DIM + h * 32 + c * 4;
                float4 xq = *(const float4*)(q + ga);
                float4 xk = *(const float4*)(k + ga);
                float4 xv = *(const float4*)(v + ga);
                cvt2(xq.x * SC, xq.y * SC, qh.x, ql.x);
                cvt2(xq.z * SC, xq.w * SC, qh.y, ql.y);
                cvt2(xk.x, xk.y, kh.x, kl.x);
                cvt2(xk.z, xk.w, kh.y, kl.y);
                cvt2(xv.x, xv.y, vh.x, vl.x);
                cvt2(xv.z, xv.w, vh.y, vl.y);
            }
            *(uint2*)(S + QHI + off) = qh;  *(uint2*)(S + QLO + off) = ql;
            *(uint2*)(S + KHI + off) = kh;  *(uint2*)(S + KLO + off) = kl;
            *(uint2*)(S + VHI + off) = vh;  *(uint2*)(S + VLO + off) = vl;
        }
    }

    // ---- bias -> accumulator init (tiles 2*warp, 2*warp+1) ----
    float acc[2][7][4];
    #pragma unroll
    for (int t2 = 0; t2 < 2; ++t2) {
        const float4* bt = g_bias4 + ((h * 4 + (warp * 2 + t2)) * 7) * 32 + lane;
        #pragma unroll
        for (int j = 0; j < 7; ++j) {
            float4 bv = __ldg(bt + j * 32);
            acc[t2][j][0] = bv.x;  acc[t2][j][1] = bv.y;
            acc[t2][j][2] = bv.z;  acc[t2][j][3] = bv.w;
        }
    }
    __syncthreads();

    // ---- q A-fragments via ldmatrix (2 m16 tiles) ----
    uint32_t qh0[2][4], qh1[2][4], ql0[2][4], ql1[2][4];
    #pragma unroll
    for (int t2 = 0; t2 < 2; ++t2) {
        const uint32_t aP = sb + QHI +
            (uint32_t)((warp * 32 + t2 * 16 + POFF) * RS + CG * 16);
        ldsm4(qh0[t2], aP);
        ldsm4(qh1[t2], aP + 32);
        ldsm4(ql0[t2], aP + (QLO - QHI));
        ldsm4(ql1[t2], aP + (QLO - QHI) + 32);
    }

    // ---- QK: bias + q @ k^T  (hi*hi + lo*hi + hi*lo); k frags shared ----
    {
        const uint32_t bP = sb + KHI + (uint32_t)((lane & 7) * RS + (lane >> 3) * 16);
        #pragma unroll
        for (int j = 0; j < 7; ++j) {
            uint32_t bh[4], bl[4];
            ldsm4(bh, bP + (uint32_t)(j * 8 * RS));
            #pragma unroll
            for (int t2 = 0; t2 < 2; ++t2) {
                mma16816(acc[t2][j], qh0[t2], bh[0], bh[1]);
                mma16816(acc[t2][j], qh1[t2], bh[2], bh[3]);
                mma16816(acc[t2][j], ql0[t2], bh[0], bh[1]);
                mma16816(acc[t2][j], ql1[t2], bh[2], bh[3]);
            }
            ldsm4(bl, bP + (uint32_t)(j * 8 * RS) + (KLO - KHI));
            #pragma unroll
            for (int t2 = 0; t2 < 2; ++t2) {
                mma16816(acc[t2][j], qh0[t2], bl[0], bl[1]);
                mma16816(acc[t2][j], qh1[t2], bl[2], bl[3]);
            }
        }
    }

    // ---- softmax in-place on acc (per tile: rows n1, n2; quad-local) ----
    float rinv1[2], rinv2[2];
    #pragma unroll
    for (int t2 = 0; t2 < 2; ++t2) {
        float mx1 = acc[t2][0][0], mx2 = acc[t2][0][2];
        #pragma unroll
        for (int j = 0; j < 7; ++j) {
            mx1 = fmaxf(mx1, fmaxf(acc[t2][j][0], acc[t2][j][1]));
            mx2 = fmaxf(mx2, fmaxf(acc[t2][j][2], acc[t2][j][3]));
        }
        mx1 = fmaxf(mx1, __shfl_xor_sync(0xffffffffu, mx1, 1));
        mx1 = fmaxf(mx1, __shfl_xor_sync(0xffffffffu, mx1, 2));
        mx2 = fmaxf(mx2, __shfl_xor_sync(0xffffffffu, mx2, 1));
        mx2 = fmaxf(mx2, __shfl_xor_sync(0xffffffffu, mx2, 2));
        float sum1 = 0.0f, sum2 = 0.0f;
        #pragma unroll
        for (int j = 0; j < 7; ++j) {
            acc[t2][j][0] = __expf(acc[t2][j][0] - mx1); sum1 += acc[t2][j][0];
            acc[t2][j][1] = __expf(acc[t2][j][1] - mx1); sum1 += acc[t2][j][1];
            acc[t2][j][2] = __expf(acc[t2][j][2] - mx2); sum2 += acc[t2][j][2];
            acc[t2][j][3] = __expf(acc[t2][j][3] - mx2); sum2 += acc[t2][j][3];
        }
        sum1 += __shfl_xor_sync(0xffffffffu, sum1, 1);
        sum1 += __shfl_xor_sync(0xffffffffu, sum1, 2);
        sum2 += __shfl_xor_sync(0xffffffffu, sum2, 1);
        sum2 += __shfl_xor_sync(0xffffffffu, sum2, 2);
        rinv1[t2] = 1.0f / sum1;
        rinv2[t2] = 1.0f / sum2;
    }

    // ---- PV: O = e @ v; v frags shared across tiles, e converted lazily ----
    float o[2][4][4];
    #pragma unroll
    for (int t2 = 0; t2 < 2; ++t2)
        #pragma unroll
        for (int j = 0; j < 4; ++j)
            #pragma unroll
            for (int c = 0; c < 4; ++c) o[t2][j][c] = 0.0f;

    {
        const uint32_t vP = sb + VHI + (uint32_t)(POFF * RS + CG * 16);
        #pragma unroll
        for (int t = 0; t < 4; ++t) {
            uint32_t vah[4], vbh[4], val[4], vbl[4];
            const uint32_t base = vP + (uint32_t)(t * 16 * RS);
            ldsm4t(vah, base);
            ldsm4t(vbh, base + 32);
            ldsm4t(val, base + (VLO - VHI));
            ldsm4t(vbl, base + (VLO - VHI) + 32);
            #pragma unroll
            for (int t2 = 0; t2 < 2; ++t2) {
                uint32_t ehf[4], elf[4];
                if (t < 3) {
                    cvt2(acc[t2][2*t][0],   acc[t2][2*t][1],   ehf[0], elf[0]);
                    cvt2(acc[t2][2*t][2],   acc[t2][2*t][3],   ehf[1], elf[1]);
                    cvt2(acc[t2][2*t+1][0], acc[t2][2*t+1][1], ehf[2], elf[2]);
                    cvt2(acc[t2][2*t+1][2], acc[t2][2*t+1][3], ehf[3], elf[3]);
                } else {
                    cvt2(acc[t2][6][0], acc[t2][6][1], ehf[0], elf[0]);
                    cvt2(acc[t2][6][2], acc[t2][6][3], ehf[1], elf[1]);
                    ehf[2] = 0u; elf[2] = 0u;
                    ehf[3] = 0u; elf[3] = 0u;
                }
                mma16816(o[t2][0], ehf, vah[0], vah[1]);
                mma16816(o[t2][1], ehf, vah[2], vah[3]);
                mma16816(o[t2][2], ehf, vbh[0], vbh[1]);
                mma16816(o[t2][3], ehf, vbh[2], vbh[3]);
                mma16816(o[t2][0], elf, vah[0], vah[1]);
                mma16816(o[t2][1], elf, vah[2], vah[3]);
                mma16816(o[t2][2], elf, vbh[0], vbh[1]);
                mma16816(o[t2][3], elf, vbh[2], vbh[3]);
                mma16816(o[t2][0], ehf, val[0], val[1]);
                mma16816(o[t2][1], ehf, val[2], val[3]);
                mma16816(o[t2][2], ehf, vbl[0], vbl[1]);
                mma16816(o[t2][3], ehf, vbl[2], vbl[3]);
            }
        }
    }

    // ---- normalize + store ----
    #pragma unroll
    for (int t2 = 0; t2 < 2; ++t2) {
        const int n1 = warp * 32 + t2 * 16 + g;
        const int n2 = n1 + 8;
        if (n1 < N_TOK) {
            float* op = out + wbase + (size_t)n1 * C_DIM + h * 32;
            #pragma unroll
            for (int j = 0; j < 4; ++j)
                *(float2*)(op + 8 * j + 2 * tig) =
                    make_float2(o[t2][j][0] * rinv1[t2], o[t2][j][1] * rinv1[t2]);
        }
        if (n2 < N_TOK) {
            float* op = out + wbase + (size_t)n2 * C_DIM + h * 32;
            #pragma unroll
            for (int j = 0; j < 4; ++j)
                *(float2*)(op + 8 * j + 2 * tig) =
                    make_float2(o[t2][j][2] * rinv2[t2], o[t2][j][3] * rinv2[t2]);
        }
    }
}

// ---------------------------------------------------------------------------
extern "C" void kernel_launch(void* const* d_in, const int* in_sizes, int n_in,
                              void* d_out, int out_size) {
    const float* q       = (const float*)d_in[0];
    const float* k       = (const float*)d_in[1];
    const float* v       = (const float*)d_in[2];
    const float* rel_pos = (const float*)d_in[3];
    const float* w1      = (const float*)d_in[4];
    const float* b1      = (const float*)d_in[5];
    const float* w2      = (const float*)d_in[6];
    const float* b2      = (const float*)d_in[7];
    float* out = (float*)d_out;

    const int nwin = in_sizes[0] / (N_TOK * C_DIM);

    bias_kernel<<<(64 * 56 * 8 + 127) / 128, 128>>>(rel_pos, w1, b1, w2, b2);
    dim3 grid(nwin, 3);
    attn_kernel<<<grid, 64>>>(q, k, v, out);
}

// round 12
// speedup vs baseline: 1.1641x; 1.1641x over previous
#include <cuda_runtime.h>
#include <cuda_bf16.h>
#include <cstdint>

#define N_TOK 49
#define C_DIM 96
#define RS 80          // row stride bytes (64B data + 16B pad)
#define QHI 0
#define QLO 5120
#define KHI 10240
#define KLO 15360
#define VHI 20480
#define VLO 25600
#define SMEM_BYTES 30720
#define OB_STRIDE 36   // obuf row stride in floats (144B, 16B-aligned)

__device__ float4 g_bias4[3 * 4 * 7 * 32];  // C-fragment-ordered bias table

// ---------------------------------------------------------------------------
__device__ __forceinline__ uint32_t smem_u32(const void* p) {
    uint32_t a;
    asm("{ .reg .u64 t; cvta.to.shared.u64 t, %1; cvt.u32.u64 %0, t; }" : "=r"(a) : "l"(p));
    return a;
}
__device__ __forceinline__ void ldsm4(uint32_t r[4], uint32_t addr) {
    asm volatile("ldmatrix.sync.aligned.m8n8.x4.shared.b16 {%0,%1,%2,%3}, [%4];"
                 : "=r"(r[0]), "=r"(r[1]), "=r"(r[2]), "=r"(r[3]) : "r"(addr));
}
__device__ __forceinline__ void ldsm4t(uint32_t r[4], uint32_t addr) {
    asm volatile("ldmatrix.sync.aligned.m8n8.x4.trans.shared.b16 {%0,%1,%2,%3}, [%4];"
                 : "=r"(r[0]), "=r"(r[1]), "=r"(r[2]), "=r"(r[3]) : "r"(addr));
}
__device__ __forceinline__ void mma16816(float c[4], const uint32_t a[4],
                                         uint32_t b0, uint32_t b1) {
    asm volatile(
        "mma.sync.aligned.m16n8k16.row.col.f32.bf16.bf16.f32 "
        "{%0,%1,%2,%3}, {%4,%5,%6,%7}, {%8,%9}, {%0,%1,%2,%3};"
        : "+f"(c[0]), "+f"(c[1]), "+f"(c[2]), "+f"(c[3])
        : "r"(a[0]), "r"(a[1]), "r"(a[2]), "r"(a[3]), "r"(b0), "r"(b1));
}
// split (x,y) into packed bf16 hi + bf16 lo (x ~= hi + lo)
__device__ __forceinline__ void cvt2(float x, float y, uint32_t& hi, uint32_t& lo) {
    __nv_bfloat162 h = __floats2bfloat162_rn(x, y);
    float hx = __bfloat162float(__low2bfloat16(h));
    float hy = __bfloat162float(__high2bfloat16(h));
    __nv_bfloat162 l = __floats2bfloat162_rn(x - hx, y - hy);
    hi = *reinterpret_cast<uint32_t*>(&h);
    lo = *reinterpret_cast<uint32_t*>(&l);
}

// ---------------------------------------------------------------------------
// Bias MLP, slice-parallel (8 lanes per position), writing DIRECTLY into the
// C-fragment-ordered table g_bias4 ([h][m16-tile][j][lane]).
// ---------------------------------------------------------------------------
__global__ void bias_kernel(const float* __restrict__ rel_pos,
                            const float* __restrict__ w1,
                            const float* __restrict__ b1,
                            const float* __restrict__ w2,
                            const float* __restrict__ b2) {
    int gid = blockIdx.x * blockDim.x + threadIdx.x;
    if (gid >= 64 * 56 * 8) return;
    const int s = gid & 7;          // hidden-slice index
    const int p = gid >> 3;         // position [0, 3584)
    const int n = p / 56;
    const int m = p - n * 56;

    float a0 = 0.f, a1 = 0.f, a2 = 0.f;
    const bool live = (n < N_TOK) && (m < N_TOK);
    if (live) {
        const int idx = n * N_TOK + m;
        const float r0 = rel_pos[2 * idx + 0];
        const float r1 = rel_pos[2 * idx + 1];
        const int j0 = s * 32;
        #pragma unroll 8
        for (int j = j0; j < j0 + 32; ++j) {
            float hj = fmaf(r0, __ldg(w1 + j), fmaf(r1, __ldg(w1 + 256 + j), __ldg(b1 + j)));
            hj = fmaxf(hj, 0.0f);
            a0 = fmaf(hj, __ldg(w2 + j * 3 + 0), a0);
            a1 = fmaf(hj, __ldg(w2 + j * 3 + 1), a1);
            a2 = fmaf(hj, __ldg(w2 + j * 3 + 2), a2);
        }
    }
    #pragma unroll
    for (int o = 1; o < 8; o <<= 1) {
        a0 += __shfl_xor_sync(0xffffffffu, a0, o);
        a1 += __shfl_xor_sync(0xffffffffu, a1, o);
        a2 += __shfl_xor_sync(0xffffffffu, a2, o);
    }
    if (s == 0) {
        float v0, v1, v2;
        if (m >= N_TOK)      { v0 = v1 = v2 = -1e30f; }
        else if (n >= N_TOK) { v0 = v1 = v2 = 0.0f; }
        else { v0 = a0 + __ldg(b2 + 0); v1 = a1 + __ldg(b2 + 1); v2 = a2 + __ldg(b2 + 2); }
        const int w    = n >> 4;
        const int half = (n >> 3) & 1;
        const int g    = n & 7;
        const int j    = m >> 3;
        const int tig  = (m & 7) >> 1;
        const int comp = m & 1;
        const int lane4 = g * 4 + tig;
        const int fi    = half * 2 + comp;
        float* base = (float*)g_bias4 + fi;
        base[(((0 * 4 + w) * 7 + j) * 32 + lane4) * 4] = v0;
        base[(((1 * 4 + w) * 7 + j) * 32 + lane4) * 4] = v1;
        base[(((2 * 4 + w) * 7 + j) * 32 + lane4) * 4] = v2;
    }
}

// ---------------------------------------------------------------------------
// CTA = (window, head). 4 warps, warp = 16-row M-tile.
// q/k/v staged to smem as bf16 hi/lo; all fragments via ldmatrix.
// Bias preloaded coalesced (fragment-ordered table) as accumulator init.
// e stays in registers. j=7 all-pad column block skipped.
// Output staged through smem (overlaying dead q region) -> coalesced STG.128.
// ---------------------------------------------------------------------------
__global__ __launch_bounds__(128, 6)
void attn_kernel(const float* __restrict__ q,
                 const float* __restrict__ k,
                 const float* __restrict__ v,
                 float*       __restrict__ out) {
    __shared__ __align__(16) char S[SMEM_BYTES];
    const uint32_t sb = smem_u32(S);
    float* obuf = (float*)S;   // overlays q hi/lo region after q-ldsm

    const int tid  = threadIdx.x;
    const int lane = tid & 31;
    const int warp = tid >> 5;
    const int g    = lane >> 2;
    const int tig  = lane & 3;
    const int r0   = warp * 16;
    const int POFF = (lane & 7) + 8 * ((lane >> 3) & 1);
    const int CG   = lane >> 4;
    const int h    = blockIdx.y;
    const size_t wbase = (size_t)blockIdx.x * (N_TOK * C_DIM);
    const int n1 = r0 + g, n2 = n1 + 8;

    // ---- stage q (scaled), k, v as bf16 hi/lo; zero pad rows 49..63 ----
    {
        const float SC = 0.17677669529663687f;  // 1/sqrt(32)
        #pragma unroll
        for (int it = 0; it < 4; ++it) {
            int i = tid + it * 128;            // 512 = 64 rows x 8 chunks
            int n = i >> 3, c = i & 7;
            uint32_t off = (uint32_t)(n * RS + c * 8);
            uint2 qh = make_uint2(0, 0), ql = qh, kh = qh, kl = qh, vh = qh, vl = qh;
            if (n < N_TOK) {
                size_t ga = wbase + (size_t)n * C_DIM + h * 32 + c * 4;
                float4 xq = *(const float4*)(q + ga);
                float4 xk = *(const float4*)(k + ga);
                float4 xv = *(const float4*)(v + ga);
                cvt2(xq.x * SC, xq.y * SC, qh.x, ql.x);
                cvt2(xq.z * SC, xq.w * SC, qh.y, ql.y);
                cvt2(xk.x, xk.y, kh.x, kl.x);
                cvt2(xk.z, xk.w, kh.y, kl.y);
                cvt2(xv.x, xv.y, vh.x, vl.x);
                cvt2(xv.z, xv.w, vh.y, vl.y);
            }
            *(uint2*)(S + QHI + off) = qh;  *(uint2*)(S + QLO + off) = ql;
            *(uint2*)(S + KHI + off) = kh;  *(uint2*)(S + KLO + off) = kl;
            *(uint2*)(S + VHI + off) = vh;  *(uint2*)(S + VLO + off) = vl;
        }
    }

    // ---- bias -> accumulator init (coalesced fragment-ordered table) ----
    float acc[7][4];
    {
        const float4* bt = g_bias4 + ((h * 4 + warp) * 7) * 32 + lane;
        #pragma unroll
        for (int j = 0; j < 7; ++j) {
            float4 bv = __ldg(bt + j * 32);
            acc[j][0] = bv.x;  acc[j][1] = bv.y;
            acc[j][2] = bv.z;  acc[j][3] = bv.w;
        }
    }
    __syncthreads();

    // ---- q A-fragments via ldmatrix ----
    uint32_t qh0[4], qh1[4], ql0[4], ql1[4];
    {
        const uint32_t aP = sb + QHI + (uint32_t)((r0 + POFF) * RS + CG * 16);
        ldsm4(qh0, aP);
        ldsm4(qh1, aP + 32);
        ldsm4(ql0, aP + (QLO - QHI));
        ldsm4(ql1, aP + (QLO - QHI) + 32);
    }
    __syncthreads();   // q region dead -> obuf may overlay it later

    // ---- QK: S[64x56] = bias + q @ k^T  (hi*hi + lo*hi + hi*lo) ----
    {
        const uint32_t bP = sb + KHI + (uint32_t)((lane & 7) * RS + (lane >> 3) * 16);
        #pragma unroll
        for (int j = 0; j < 7; ++j) {
            uint32_t bh[4], bl[4];
            ldsm4(bh, bP + (uint32_t)(j * 8 * RS));
            mma16816(acc[j], qh0, bh[0], bh[1]);
            mma16816(acc[j], qh1, bh[2], bh[3]);
            mma16816(acc[j], ql0, bh[0], bh[1]);
            mma16816(acc[j], ql1, bh[2], bh[3]);
            ldsm4(bl, bP + (uint32_t)(j * 8 * RS) + (KLO - KHI));
            mma16816(acc[j], qh0, bl[0], bl[1]);
            mma16816(acc[j], qh1, bl[2], bl[3]);
        }
    }

    // ---- softmax in-place on acc (rows n1, n2; quad-local reductions) ----
    float mx1 = acc[0][0], mx2 = acc[0][2];
    #pragma unroll
    for (int j = 0; j < 7; ++j) {
        mx1 = fmaxf(mx1, fmaxf(acc[j][0], acc[j][1]));
        mx2 = fmaxf(mx2, fmaxf(acc[j][2], acc[j][3]));
    }
    mx1 = fmaxf(mx1, __shfl_xor_sync(0xffffffffu, mx1, 1));
    mx1 = fmaxf(mx1, __shfl_xor_sync(0xffffffffu, mx1, 2));
    mx2 = fmaxf(mx2, __shfl_xor_sync(0xffffffffu, mx2, 1));
    mx2 = fmaxf(mx2, __shfl_xor_sync(0xffffffffu, mx2, 2));
    float sum1 = 0.0f, sum2 = 0.0f;
    #pragma unroll
    for (int j = 0; j < 7; ++j) {
        acc[j][0] = __expf(acc[j][0] - mx1); sum1 += acc[j][0];
        acc[j][1] = __expf(acc[j][1] - mx1); sum1 += acc[j][1];
        acc[j][2] = __expf(acc[j][2] - mx2); sum2 += acc[j][2];
        acc[j][3] = __expf(acc[j][3] - mx2); sum2 += acc[j][3];
    }
    sum1 += __shfl_xor_sync(0xffffffffu, sum1, 1);
    sum1 += __shfl_xor_sync(0xffffffffu, sum1, 2);
    sum2 += __shfl_xor_sync(0xffffffffu, sum2, 1);
    sum2 += __shfl_xor_sync(0xffffffffu, sum2, 2);
    const float rinv1 = 1.0f / sum1;
    const float rinv2 = 1.0f / sum2;

    // ---- e A-fragments in registers (cols 56..63 -> zero) ----
    uint32_t eh[4][4], el[4][4];
    #pragma unroll
    for (int t = 0; t < 3; ++t) {
        cvt2(acc[2*t][0],   acc[2*t][1],   eh[t][0], el[t][0]);
        cvt2(acc[2*t][2],   acc[2*t][3],   eh[t][1], el[t][1]);
        cvt2(acc[2*t+1][0], acc[2*t+1][1], eh[t][2], el[t][2]);
        cvt2(acc[2*t+1][2], acc[2*t+1][3], eh[t][3], el[t][3]);
    }
    cvt2(acc[6][0], acc[6][1], eh[3][0], el[3][0]);
    cvt2(acc[6][2], acc[6][3], eh[3][1], el[3][1]);
    eh[3][2] = 0u; el[3][2] = 0u;
    eh[3][3] = 0u; el[3][3] = 0u;

    // ---- PV: O[64x32] = e @ v  (hi*hi + lo*hi + hi*lo) ----
    float o[4][4];
    #pragma unroll
    for (int j = 0; j < 4; ++j)
        #pragma unroll
        for (int c = 0; c < 4; ++c) o[j][c] = 0.0f;

    {
        const uint32_t vP = sb + VHI + (uint32_t)(POFF * RS + CG * 16);
        #pragma unroll
        for (int t = 0; t < 4; ++t) {
            uint32_t va[4], vb[4];
            const uint32_t base = vP + (uint32_t)(t * 16 * RS);
            ldsm4t(va, base);
            ldsm4t(vb, base + 32);
            mma16816(o[0], eh[t], va[0], va[1]);
            mma16816(o[1], eh[t], va[2], va[3]);
            mma16816(o[2], eh[t], vb[0], vb[1]);
            mma16816(o[3], eh[t], vb[2], vb[3]);
            mma16816(o[0], el[t], va[0], va[1]);
            mma16816(o[1], el[t], va[2], va[3]);
            mma16816(o[2], el[t], vb[0], vb[1]);
            mma16816(o[3], el[t], vb[2], vb[3]);
            ldsm4t(va, base + (VLO - VHI));
            ldsm4t(vb, base + (VLO - VHI) + 32);
            mma16816(o[0], eh[t], va[0], va[1]);
            mma16816(o[1], eh[t], va[2], va[3]);
            mma16816(o[2], eh[t], vb[0], vb[1]);
            mma16816(o[3], eh[t], vb[2], vb[3]);
        }
    }

    // ---- normalize -> smem obuf (rows n1, n2; stride 36 floats) ----
    {
        float* p1 = obuf + n1 * OB_STRIDE + 2 * tig;
        float* p2 = obuf + n2 * OB_STRIDE + 2 * tig;
        #pragma unroll
        for (int j = 0; j < 4; ++j) {
            *(float2*)(p1 + 8 * j) = make_float2(o[j][0] * rinv1, o[j][1] * rinv1);
            *(float2*)(p2 + 8 * j) = make_float2(o[j][2] * rinv2, o[j][3] * rinv2);
        }
    }
    __syncthreads();

    // ---- coalesced copy obuf -> out (49 rows x 32 floats = 392 float4) ----
    {
        float* ob = out + wbase + h * 32;
        #pragma unroll
        for (int it = 0; it < 4; ++it) {
            int i = tid + it * 128;
            if (i < N_TOK * 8) {
                int row = i >> 3, c4 = i & 7;
                float4 val = *(float4*)(obuf + row * OB_STRIDE + c4 * 4);
                *(float4*)(ob + (size_t)row * C_DIM + c4 * 4) = val;
            }
        }
    }
}

// ---------------------------------------------------------------------------
extern "C" void kernel_launch(void* const* d_in, const int* in_sizes, int n_in,
                              void* d_out, int out_size) {
    const float* q       = (const float*)d_in[0];
    const float* k       = (const float*)d_in[1];
    const float* v       = (const float*)d_in[2];
    const float* rel_pos = (const float*)d_in[3];
    const float* w1      = (const float*)d_in[4];
    const float* b1      = (const float*)d_in[5];
    const float* w2      = (const float*)d_in[6];
    const float* b2      = (const float*)d_in[7];
    float* out = (float*)d_out;

    const int nwin = in_sizes[0] / (N_TOK * C_DIM);

    bias_kernel<<<(64 * 56 * 8 + 127) / 128, 128>>>(rel_pos, w1, b1, w2, b2);
    dim3 grid(nwin, 3);
    attn_kernel<<<grid, 128>>>(q, k, v, out);
}

// round 13
// speedup vs baseline: 1.3558x; 1.1646x over previous
#include <cuda_runtime.h>
#include <cuda_bf16.h>
#include <cuda_fp16.h>
#include <cstdint>

#define N_TOK 49
#define C_DIM 96
#define RS 80          // row stride bytes (64B data + 16B pad)
#define QHI 0
#define QLO 5120
#define KHI 10240
#define KLO 15360
#define VHI 20480
#define SMEM_BYTES 25600

__device__ float4 g_bias4[3 * 4 * 7 * 32];  // C-fragment-ordered bias table

// ---------------------------------------------------------------------------
__device__ __forceinline__ uint32_t smem_u32(const void* p) {
    uint32_t a;
    asm("{ .reg .u64 t; cvta.to.shared.u64 t, %1; cvt.u32.u64 %0, t; }" : "=r"(a) : "l"(p));
    return a;
}
__device__ __forceinline__ void ldsm4(uint32_t r[4], uint32_t addr) {
    asm volatile("ldmatrix.sync.aligned.m8n8.x4.shared.b16 {%0,%1,%2,%3}, [%4];"
                 : "=r"(r[0]), "=r"(r[1]), "=r"(r[2]), "=r"(r[3]) : "r"(addr));
}
__device__ __forceinline__ void ldsm4t(uint32_t r[4], uint32_t addr) {
    asm volatile("ldmatrix.sync.aligned.m8n8.x4.trans.shared.b16 {%0,%1,%2,%3}, [%4];"
                 : "=r"(r[0]), "=r"(r[1]), "=r"(r[2]), "=r"(r[3]) : "r"(addr));
}
__device__ __forceinline__ void mma16816(float c[4], const uint32_t a[4],
                                         uint32_t b0, uint32_t b1) {
    asm volatile(
        "mma.sync.aligned.m16n8k16.row.col.f32.bf16.bf16.f32 "
        "{%0,%1,%2,%3}, {%4,%5,%6,%7}, {%8,%9}, {%0,%1,%2,%3};"
        : "+f"(c[0]), "+f"(c[1]), "+f"(c[2]), "+f"(c[3])
        : "r"(a[0]), "r"(a[1]), "r"(a[2]), "r"(a[3]), "r"(b0), "r"(b1));
}
__device__ __forceinline__ void mma16816h(float c[4], const uint32_t a[4],
                                          uint32_t b0, uint32_t b1) {
    asm volatile(
        "mma.sync.aligned.m16n8k16.row.col.f32.f16.f16.f32 "
        "{%0,%1,%2,%3}, {%4,%5,%6,%7}, {%8,%9}, {%0,%1,%2,%3};"
        : "+f"(c[0]), "+f"(c[1]), "+f"(c[2]), "+f"(c[3])
        : "r"(a[0]), "r"(a[1]), "r"(a[2]), "r"(a[3]), "r"(b0), "r"(b1));
}
// split (x,y) into packed bf16 hi + bf16 lo (x ~= hi + lo)
__device__ __forceinline__ void cvt2(float x, float y, uint32_t& hi, uint32_t& lo) {
    __nv_bfloat162 h = __floats2bfloat162_rn(x, y);
    float hx = __bfloat162float(__low2bfloat16(h));
    float hy = __bfloat162float(__high2bfloat16(h));
    __nv_bfloat162 l = __floats2bfloat162_rn(x - hx, y - hy);
    hi = *reinterpret_cast<uint32_t*>(&h);
    lo = *reinterpret_cast<uint32_t*>(&l);
}
// split (x,y) into packed fp16 hi + fp16 lo
__device__ __forceinline__ void cvt2h(float x, float y, uint32_t& hi, uint32_t& lo) {
    __half2 h = __floats2half2_rn(x, y);
    float hx = __low2float(h);
    float hy = __high2float(h);
    __half2 l = __floats2half2_rn(x - hx, y - hy);
    hi = *reinterpret_cast<uint32_t*>(&h);
    lo = *reinterpret_cast<uint32_t*>(&l);
}
__device__ __forceinline__ uint32_t pkh2(float x, float y) {
    __half2 h = __floats2half2_rn(x, y);
    return *reinterpret_cast<uint32_t*>(&h);
}

// ---------------------------------------------------------------------------
// Bias MLP, slice-parallel (8 lanes per position), writing DIRECTLY into the
// C-fragment-ordered table g_bias4 ([h][m16-tile][j][lane]).
// ---------------------------------------------------------------------------
__global__ void bias_kernel(const float* __restrict__ rel_pos,
                            const float* __restrict__ w1,
                            const float* __restrict__ b1,
                            const float* __restrict__ w2,
                            const float* __restrict__ b2) {
    int gid = blockIdx.x * blockDim.x + threadIdx.x;
    if (gid >= 64 * 56 * 8) return;
    const int s = gid & 7;          // hidden-slice index
    const int p = gid >> 3;         // position [0, 3584)
    const int n = p / 56;
    const int m = p - n * 56;

    float a0 = 0.f, a1 = 0.f, a2 = 0.f;
    const bool live = (n < N_TOK) && (m < N_TOK);
    if (live) {
        const int idx = n * N_TOK + m;
        const float r0 = rel_pos[2 * idx + 0];
        const float r1 = rel_pos[2 * idx + 1];
        const int j0 = s * 32;
        #pragma unroll 8
        for (int j = j0; j < j0 + 32; ++j) {
            float hj = fmaf(r0, __ldg(w1 + j), fmaf(r1, __ldg(w1 + 256 + j), __ldg(b1 + j)));
            hj = fmaxf(hj, 0.0f);
            a0 = fmaf(hj, __ldg(w2 + j * 3 + 0), a0);
            a1 = fmaf(hj, __ldg(w2 + j * 3 + 1), a1);
            a2 = fmaf(hj, __ldg(w2 + j * 3 + 2), a2);
        }
    }
    #pragma unroll
    for (int o = 1; o < 8; o <<= 1) {
        a0 += __shfl_xor_sync(0xffffffffu, a0, o);
        a1 += __shfl_xor_sync(0xffffffffu, a1, o);
        a2 += __shfl_xor_sync(0xffffffffu, a2, o);
    }
    if (s == 0) {
        float v0, v1, v2;
        if (m >= N_TOK)      { v0 = v1 = v2 = -1e30f; }
        else if (n >= N_TOK) { v0 = v1 = v2 = 0.0f; }
        else { v0 = a0 + __ldg(b2 + 0); v1 = a1 + __ldg(b2 + 1); v2 = a2 + __ldg(b2 + 2); }
        const int w    = n >> 4;
        const int half = (n >> 3) & 1;
        const int g    = n & 7;
        const int j    = m >> 3;
        const int tig  = (m & 7) >> 1;
        const int comp = m & 1;
        const int lane4 = g * 4 + tig;
        const int fi    = half * 2 + comp;
        float* base = (float*)g_bias4 + fi;
        base[(((0 * 4 + w) * 7 + j) * 32 + lane4) * 4] = v0;
        base[(((1 * 4 + w) * 7 + j) * 32 + lane4) * 4] = v1;
        base[(((2 * 4 + w) * 7 + j) * 32 + lane4) * 4] = v2;
    }
}

// ---------------------------------------------------------------------------
// CTA = (window, head). 4 warps, warp = 16-row M-tile.
// QK: bf16 hi/lo 3-term (q/k staged hi+lo). PV: fp16 2-term — e split hi/lo
// in REGISTERS (exact), v staged as SINGLE fp16 (halves PV ldsm + v STS).
// Bias preloaded coalesced as accumulator init. j=7 all-pad block skipped.
// ---------------------------------------------------------------------------
__global__ __launch_bounds__(128, 6)
void attn_kernel(const float* __restrict__ q,
                 const float* __restrict__ k,
                 const float* __restrict__ v,
                 float*       __restrict__ out) {
    __shared__ __align__(16) char S[SMEM_BYTES];
    const uint32_t sb = smem_u32(S);

    const int tid  = threadIdx.x;
    const int lane = tid & 31;
    const int warp = tid >> 5;
    const int g    = lane >> 2;
    const int tig  = lane & 3;
    const int r0   = warp * 16;
    const int POFF = (lane & 7) + 8 * ((lane >> 3) & 1);
    const int CG   = lane >> 4;
    const int h    = blockIdx.y;
    const size_t wbase = (size_t)blockIdx.x * (N_TOK * C_DIM);
    const int n1 = r0 + g, n2 = n1 + 8;

    // ---- stage q (scaled) / k as bf16 hi+lo, v as single fp16 ----
    {
        const float SC = 0.17677669529663687f;  // 1/sqrt(32)
        #pragma unroll
        for (int it = 0; it < 4; ++it) {
            int i = tid + it * 128;            // 512 = 64 rows x 8 chunks
            int n = i >> 3, c = i & 7;
            uint32_t off = (uint32_t)(n * RS + c * 8);
            uint2 qh = make_uint2(0, 0), ql = qh, kh = qh, kl = qh, vh = qh;
            if (n < N_TOK) {
                size_t ga = wbase + (size_t)n * C_DIM + h * 32 + c * 4;
                float4 xq = *(const float4*)(q + ga);
                float4 xk = *(const float4*)(k + ga);
                float4 xv = *(const float4*)(v + ga);
                cvt2(xq.x * SC, xq.y * SC, qh.x, ql.x);
                cvt2(xq.z * SC, xq.w * SC, qh.y, ql.y);
                cvt2(xk.x, xk.y, kh.x, kl.x);
                cvt2(xk.z, xk.w, kh.y, kl.y);
                vh.x = pkh2(xv.x, xv.y);
                vh.y = pkh2(xv.z, xv.w);
            }
            *(uint2*)(S + QHI + off) = qh;  *(uint2*)(S + QLO + off) = ql;
            *(uint2*)(S + KHI + off) = kh;  *(uint2*)(S + KLO + off) = kl;
            *(uint2*)(S + VHI + off) = vh;
        }
    }

    // ---- bias -> accumulator init (coalesced fragment-ordered table) ----
    float acc[7][4];
    {
        const float4* bt = g_bias4 + ((h * 4 + warp) * 7) * 32 + lane;
        #pragma unroll
        for (int j = 0; j < 7; ++j) {
            float4 bv = __ldg(bt + j * 32);
            acc[j][0] = bv.x;  acc[j][1] = bv.y;
            acc[j][2] = bv.z;  acc[j][3] = bv.w;
        }
    }
    __syncthreads();

    // ---- q A-fragments via ldmatrix ----
    uint32_t qh0[4], qh1[4], ql0[4], ql1[4];
    {
        const uint32_t aP = sb + QHI + (uint32_t)((r0 + POFF) * RS + CG * 16);
        ldsm4(qh0, aP);
        ldsm4(qh1, aP + 32);
        ldsm4(ql0, aP + (QLO - QHI));
        ldsm4(ql1, aP + (QLO - QHI) + 32);
    }

    // ---- QK: S[64x56] = bias + q @ k^T  (hi*hi + lo*hi + hi*lo, bf16) ----
    {
        const uint32_t bP = sb + KHI + (uint32_t)((lane & 7) * RS + (lane >> 3) * 16);
        #pragma unroll
        for (int j = 0; j < 7; ++j) {
            uint32_t bh[4], bl[4];
            ldsm4(bh, bP + (uint32_t)(j * 8 * RS));
            mma16816(acc[j], qh0, bh[0], bh[1]);
            mma16816(acc[j], qh1, bh[2], bh[3]);
            mma16816(acc[j], ql0, bh[0], bh[1]);
            mma16816(acc[j], ql1, bh[2], bh[3]);
            ldsm4(bl, bP + (uint32_t)(j * 8 * RS) + (KLO - KHI));
            mma16816(acc[j], qh0, bl[0], bl[1]);
            mma16816(acc[j], qh1, bl[2], bl[3]);
        }
    }

    // ---- softmax in-place on acc (rows n1, n2; quad-local reductions) ----
    float mx1 = acc[0][0], mx2 = acc[0][2];
    #pragma unroll
    for (int j = 0; j < 7; ++j) {
        mx1 = fmaxf(mx1, fmaxf(acc[j][0], acc[j][1]));
        mx2 = fmaxf(mx2, fmaxf(acc[j][2], acc[j][3]));
    }
    mx1 = fmaxf(mx1, __shfl_xor_sync(0xffffffffu, mx1, 1));
    mx1 = fmaxf(mx1, __shfl_xor_sync(0xffffffffu, mx1, 2));
    mx2 = fmaxf(mx2, __shfl_xor_sync(0xffffffffu, mx2, 1));
    mx2 = fmaxf(mx2, __shfl_xor_sync(0xffffffffu, mx2, 2));
    float sum1 = 0.0f, sum2 = 0.0f;
    #pragma unroll
    for (int j = 0; j < 7; ++j) {
        acc[j][0] = __expf(acc[j][0] - mx1); sum1 += acc[j][0];
        acc[j][1] = __expf(acc[j][1] - mx1); sum1 += acc[j][1];
        acc[j][2] = __expf(acc[j][2] - mx2); sum2 += acc[j][2];
        acc[j][3] = __expf(acc[j][3] - mx2); sum2 += acc[j][3];
    }
    sum1 += __shfl_xor_sync(0xffffffffu, sum1, 1);
    sum1 += __shfl_xor_sync(0xffffffffu, sum1, 2);
    sum2 += __shfl_xor_sync(0xffffffffu, sum2, 1);
    sum2 += __shfl_xor_sync(0xffffffffu, sum2, 2);
    const float rinv1 = 1.0f / sum1;
    const float rinv2 = 1.0f / sum2;

    // ---- e A-fragments in registers: fp16 hi + fp16 lo (cols 56..63 -> 0) ----
    uint32_t eh[4][4], el[4][4];
    #pragma unroll
    for (int t = 0; t < 3; ++t) {
        cvt2h(acc[2*t][0],   acc[2*t][1],   eh[t][0], el[t][0]);
        cvt2h(acc[2*t][2],   acc[2*t][3],   eh[t][1], el[t][1]);
        cvt2h(acc[2*t+1][0], acc[2*t+1][1], eh[t][2], el[t][2]);
        cvt2h(acc[2*t+1][2], acc[2*t+1][3], eh[t][3], el[t][3]);
    }
    cvt2h(acc[6][0], acc[6][1], eh[3][0], el[3][0]);
    cvt2h(acc[6][2], acc[6][3], eh[3][1], el[3][1]);
    eh[3][2] = 0u; el[3][2] = 0u;
    eh[3][3] = 0u; el[3][3] = 0u;

    // ---- PV: O[64x32] = (e_hi + e_lo) @ v_f16  (fp16 2-term) ----
    float o[4][4];
    #pragma unroll
    for (int j = 0; j < 4; ++j)
        #pragma unroll
        for (int c = 0; c < 4; ++c) o[j][c] = 0.0f;

    {
        const uint32_t vP = sb + VHI + (uint32_t)(POFF * RS + CG * 16);
        #pragma unroll
        for (int t = 0; t < 4; ++t) {
            uint32_t va[4], vb[4];
            const uint32_t base = vP + (uint32_t)(t * 16 * RS);
            ldsm4t(va, base);
            ldsm4t(vb, base + 32);
            mma16816h(o[0], eh[t], va[0], va[1]);
            mma16816h(o[1], eh[t], va[2], va[3]);
            mma16816h(o[2], eh[t], vb[0], vb[1]);
            mma16816h(o[3], eh[t], vb[2], vb[3]);
            mma16816h(o[0], el[t], va[0], va[1]);
            mma16816h(o[1], el[t], va[2], va[3]);
            mma16816h(o[2], el[t], vb[0], vb[1]);
            mma16816h(o[3], el[t], vb[2], vb[3]);
        }
    }

    // ---- normalize + store ----
    if (n1 < N_TOK) {
        float* op = out + wbase + (size_t)n1 * C_DIM + h * 32;
        #pragma unroll
        for (int j = 0; j < 4; ++j)
            *(float2*)(op + 8 * j + 2 * tig) =
                make_float2(o[j][0] * rinv1, o[j][1] * rinv1);
    }
    if (n2 < N_TOK) {
        float* op = out + wbase + (size_t)n2 * C_DIM + h * 32;
        #pragma unroll
        for (int j = 0; j < 4; ++j)
            *(float2*)(op + 8 * j + 2 * tig) =
                make_float2(o[j][2] * rinv2, o[j][3] * rinv2);
    }
}

// ---------------------------------------------------------------------------
extern "C" void kernel_launch(void* const* d_in, const int* in_sizes, int n_in,
                              void* d_out, int out_size) {
    const float* q       = (const float*)d_in[0];
    const float* k       = (const float*)d_in[1];
    const float* v       = (const float*)d_in[2];
    const float* rel_pos = (const float*)d_in[3];
    const float* w1      = (const float*)d_in[4];
    const float* b1      = (const float*)d_in[5];
    const float* w2      = (const float*)d_in[6];
    const float* b2      = (const float*)d_in[7];
    float* out = (float*)d_out;

    const int nwin = in_sizes[0] / (N_TOK * C_DIM);

    bias_kernel<<<(64 * 56 * 8 + 127) / 128, 128>>>(rel_pos, w1, b1, w2, b2);
    dim3 grid(nwin, 3);
    attn_kernel<<<grid, 128>>>(q, k, v, out);
}

// round 14
// speedup vs baseline: 1.4591x; 1.0762x over previous
#include <cuda_runtime.h>
#include <cuda_bf16.h>
#include <cuda_fp16.h>
#include <cstdint>

#define N_TOK 49
#define C_DIM 96
#define RS 80          // row stride bytes (64B data + 16B pad)
#define QHI 0
#define QLO 5120
#define KHI 10240
#define VHI 15360
#define SMEM_BYTES 20480

__device__ float4 g_bias4[3 * 4 * 7 * 32];  // C-fragment-ordered bias table

// ---------------------------------------------------------------------------
__device__ __forceinline__ uint32_t smem_u32(const void* p) {
    uint32_t a;
    asm("{ .reg .u64 t; cvta.to.shared.u64 t, %1; cvt.u32.u64 %0, t; }" : "=r"(a) : "l"(p));
    return a;
}
__device__ __forceinline__ void ldsm4(uint32_t r[4], uint32_t addr) {
    asm volatile("ldmatrix.sync.aligned.m8n8.x4.shared.b16 {%0,%1,%2,%3}, [%4];"
                 : "=r"(r[0]), "=r"(r[1]), "=r"(r[2]), "=r"(r[3]) : "r"(addr));
}
__device__ __forceinline__ void ldsm4t(uint32_t r[4], uint32_t addr) {
    asm volatile("ldmatrix.sync.aligned.m8n8.x4.trans.shared.b16 {%0,%1,%2,%3}, [%4];"
                 : "=r"(r[0]), "=r"(r[1]), "=r"(r[2]), "=r"(r[3]) : "r"(addr));
}
__device__ __forceinline__ void mma16816h(float c[4], const uint32_t a[4],
                                          uint32_t b0, uint32_t b1) {
    asm volatile(
        "mma.sync.aligned.m16n8k16.row.col.f32.f16.f16.f32 "
        "{%0,%1,%2,%3}, {%4,%5,%6,%7}, {%8,%9}, {%0,%1,%2,%3};"
        : "+f"(c[0]), "+f"(c[1]), "+f"(c[2]), "+f"(c[3])
        : "r"(a[0]), "r"(a[1]), "r"(a[2]), "r"(a[3]), "r"(b0), "r"(b1));
}
// split (x,y) into packed fp16 hi + fp16 lo (x ~= hi + lo)
__device__ __forceinline__ void cvt2h(float x, float y, uint32_t& hi, uint32_t& lo) {
    __half2 h = __floats2half2_rn(x, y);
    float hx = __low2float(h);
    float hy = __high2float(h);
    __half2 l = __floats2half2_rn(x - hx, y - hy);
    hi = *reinterpret_cast<uint32_t*>(&h);
    lo = *reinterpret_cast<uint32_t*>(&l);
}
__device__ __forceinline__ uint32_t pkh2(float x, float y) {
    __half2 h = __floats2half2_rn(x, y);
    return *reinterpret_cast<uint32_t*>(&h);
}

// ---------------------------------------------------------------------------
// Bias MLP, slice-parallel (8 lanes per position), writing DIRECTLY into the
// C-fragment-ordered table g_bias4 ([h][m16-tile][j][lane]).
// ---------------------------------------------------------------------------
__global__ void bias_kernel(const float* __restrict__ rel_pos,
                            const float* __restrict__ w1,
                            const float* __restrict__ b1,
                            const float* __restrict__ w2,
                            const float* __restrict__ b2) {
    int gid = blockIdx.x * blockDim.x + threadIdx.x;
    if (gid >= 64 * 56 * 8) return;
    const int s = gid & 7;          // hidden-slice index
    const int p = gid >> 3;         // position [0, 3584)
    const int n = p / 56;
    const int m = p - n * 56;

    float a0 = 0.f, a1 = 0.f, a2 = 0.f;
    const bool live = (n < N_TOK) && (m < N_TOK);
    if (live) {
        const int idx = n * N_TOK + m;
        const float r0 = rel_pos[2 * idx + 0];
        const float r1 = rel_pos[2 * idx + 1];
        const int j0 = s * 32;
        #pragma unroll 8
        for (int j = j0; j < j0 + 32; ++j) {
            float hj = fmaf(r0, __ldg(w1 + j), fmaf(r1, __ldg(w1 + 256 + j), __ldg(b1 + j)));
            hj = fmaxf(hj, 0.0f);
            a0 = fmaf(hj, __ldg(w2 + j * 3 + 0), a0);
            a1 = fmaf(hj, __ldg(w2 + j * 3 + 1), a1);
            a2 = fmaf(hj, __ldg(w2 + j * 3 + 2), a2);
        }
    }
    #pragma unroll
    for (int o = 1; o < 8; o <<= 1) {
        a0 += __shfl_xor_sync(0xffffffffu, a0, o);
        a1 += __shfl_xor_sync(0xffffffffu, a1, o);
        a2 += __shfl_xor_sync(0xffffffffu, a2, o);
    }
    if (s == 0) {
        float v0, v1, v2;
        if (m >= N_TOK)      { v0 = v1 = v2 = -1e30f; }
        else if (n >= N_TOK) { v0 = v1 = v2 = 0.0f; }
        else { v0 = a0 + __ldg(b2 + 0); v1 = a1 + __ldg(b2 + 1); v2 = a2 + __ldg(b2 + 2); }
        const int w    = n >> 4;
        const int half = (n >> 3) & 1;
        const int g    = n & 7;
        const int j    = m >> 3;
        const int tig  = (m & 7) >> 1;
        const int comp = m & 1;
        const int lane4 = g * 4 + tig;
        const int fi    = half * 2 + comp;
        float* base = (float*)g_bias4 + fi;
        base[(((0 * 4 + w) * 7 + j) * 32 + lane4) * 4] = v0;
        base[(((1 * 4 + w) * 7 + j) * 32 + lane4) * 4] = v1;
        base[(((2 * 4 + w) * 7 + j) * 32 + lane4) * 4] = v2;
    }
}

// ---------------------------------------------------------------------------
// CTA = (window, head). 4 warps, warp = 16-row M-tile.
// QK: fp16 2-term — q staged hi+lo (exact), k staged SINGLE fp16.
// PV: fp16 2-term — e split hi/lo in registers, v staged SINGLE fp16.
// Bias preloaded coalesced as accumulator init. j=7 all-pad block skipped.
// ---------------------------------------------------------------------------
__global__ __launch_bounds__(128, 6)
void attn_kernel(const float* __restrict__ q,
                 const float* __restrict__ k,
                 const float* __restrict__ v,
                 float*       __restrict__ out) {
    __shared__ __align__(16) char S[SMEM_BYTES];
    const uint32_t sb = smem_u32(S);

    const int tid  = threadIdx.x;
    const int lane = tid & 31;
    const int warp = tid >> 5;
    const int g    = lane >> 2;
    const int tig  = lane & 3;
    const int r0   = warp * 16;
    const int POFF = (lane & 7) + 8 * ((lane >> 3) & 1);
    const int CG   = lane >> 4;
    const int h    = blockIdx.y;
    const size_t wbase = (size_t)blockIdx.x * (N_TOK * C_DIM);
    const int n1 = r0 + g, n2 = n1 + 8;

    // ---- stage q (scaled, fp16 hi+lo), k and v as single fp16 ----
    {
        const float SC = 0.17677669529663687f;  // 1/sqrt(32)
        #pragma unroll
        for (int it = 0; it < 4; ++it) {
            int i = tid + it * 128;            // 512 = 64 rows x 8 chunks
            int n = i >> 3, c = i & 7;
            uint32_t off = (uint32_t)(n * RS + c * 8);
            uint2 qh = make_uint2(0, 0), ql = qh, kh = qh, vh = qh;
            if (n < N_TOK) {
                size_t ga = wbase + (size_t)n * C_DIM + h * 32 + c * 4;
                float4 xq = *(const float4*)(q + ga);
                float4 xk = *(const float4*)(k + ga);
                float4 xv = *(const float4*)(v + ga);
                cvt2h(xq.x * SC, xq.y * SC, qh.x, ql.x);
                cvt2h(xq.z * SC, xq.w * SC, qh.y, ql.y);
                kh.x = pkh2(xk.x, xk.y);
                kh.y = pkh2(xk.z, xk.w);
                vh.x = pkh2(xv.x, xv.y);
                vh.y = pkh2(xv.z, xv.w);
            }
            *(uint2*)(S + QHI + off) = qh;  *(uint2*)(S + QLO + off) = ql;
            *(uint2*)(S + KHI + off) = kh;
            *(uint2*)(S + VHI + off) = vh;
        }
    }

    // ---- bias -> accumulator init (coalesced fragment-ordered table) ----
    float acc[7][4];
    {
        const float4* bt = g_bias4 + ((h * 4 + warp) * 7) * 32 + lane;
        #pragma unroll
        for (int j = 0; j < 7; ++j) {
            float4 bv = __ldg(bt + j * 32);
            acc[j][0] = bv.x;  acc[j][1] = bv.y;
            acc[j][2] = bv.z;  acc[j][3] = bv.w;
        }
    }
    __syncthreads();

    // ---- q A-fragments via ldmatrix ----
    uint32_t qh0[4], qh1[4], ql0[4], ql1[4];
    {
        const uint32_t aP = sb + QHI + (uint32_t)((r0 + POFF) * RS + CG * 16);
        ldsm4(qh0, aP);
        ldsm4(qh1, aP + 32);
        ldsm4(ql0, aP + (QLO - QHI));
        ldsm4(ql1, aP + (QLO - QHI) + 32);
    }

    // ---- QK: S[64x56] = bias + (q_hi + q_lo) @ k_f16^T ----
    {
        const uint32_t bP = sb + KHI + (uint32_t)((lane & 7) * RS + (lane >> 3) * 16);
        #pragma unroll
        for (int j = 0; j < 7; ++j) {
            uint32_t bh[4];
            ldsm4(bh, bP + (uint32_t)(j * 8 * RS));
            mma16816h(acc[j], qh0, bh[0], bh[1]);
            mma16816h(acc[j], qh1, bh[2], bh[3]);
            mma16816h(acc[j], ql0, bh[0], bh[1]);
            mma16816h(acc[j], ql1, bh[2], bh[3]);
        }
    }

    // ---- softmax in-place on acc (rows n1, n2; quad-local reductions) ----
    float mx1 = acc[0][0], mx2 = acc[0][2];
    #pragma unroll
    for (int j = 0; j < 7; ++j) {
        mx1 = fmaxf(mx1, fmaxf(acc[j][0], acc[j][1]));
        mx2 = fmaxf(mx2, fmaxf(acc[j][2], acc[j][3]));
    }
    mx1 = fmaxf(mx1, __shfl_xor_sync(0xffffffffu, mx1, 1));
    mx1 = fmaxf(mx1, __shfl_xor_sync(0xffffffffu, mx1, 2));
    mx2 = fmaxf(mx2, __shfl_xor_sync(0xffffffffu, mx2, 1));
    mx2 = fmaxf(mx2, __shfl_xor_sync(0xffffffffu, mx2, 2));
    float sum1 = 0.0f, sum2 = 0.0f;
    #pragma unroll
    for (int j = 0; j < 7; ++j) {
        acc[j][0] = __expf(acc[j][0] - mx1); sum1 += acc[j][0];
        acc[j][1] = __expf(acc[j][1] - mx1); sum1 += acc[j][1];
        acc[j][2] = __expf(acc[j][2] - mx2); sum2 += acc[j][2];
        acc[j][3] = __expf(acc[j][3] - mx2); sum2 += acc[j][3];
    }
    sum1 += __shfl_xor_sync(0xffffffffu, sum1, 1);
    sum1 += __shfl_xor_sync(0xffffffffu, sum1, 2);
    sum2 += __shfl_xor_sync(0xffffffffu, sum2, 1);
    sum2 += __shfl_xor_sync(0xffffffffu, sum2, 2);
    const float rinv1 = 1.0f / sum1;
    const float rinv2 = 1.0f / sum2;

    // ---- e A-fragments in registers: fp16 hi + fp16 lo (cols 56..63 -> 0) ----
    uint32_t eh[4][4], el[4][4];
    #pragma unroll
    for (int t = 0; t < 3; ++t) {
        cvt2h(acc[2*t][0],   acc[2*t][1],   eh[t][0], el[t][0]);
        cvt2h(acc[2*t][2],   acc[2*t][3],   eh[t][1], el[t][1]);
        cvt2h(acc[2*t+1][0], acc[2*t+1][1], eh[t][2], el[t][2]);
        cvt2h(acc[2*t+1][2], acc[2*t+1][3], eh[t][3], el[t][3]);
    }
    cvt2h(acc[6][0], acc[6][1], eh[3][0], el[3][0]);
    cvt2h(acc[6][2], acc[6][3], eh[3][1], el[3][1]);
    eh[3][2] = 0u; el[3][2] = 0u;
    eh[3][3] = 0u; el[3][3] = 0u;

    // ---- PV: O[64x32] = (e_hi + e_lo) @ v_f16  (fp16 2-term) ----
    float o[4][4];
    #pragma unroll
    for (int j = 0; j < 4; ++j)
        #pragma unroll
        for (int c = 0; c < 4; ++c) o[j][c] = 0.0f;

    {
        const uint32_t vP = sb + VHI + (uint32_t)(POFF * RS + CG * 16);
        #pragma unroll
        for (int t = 0; t < 4; ++t) {
            uint32_t va[4], vb[4];
            const uint32_t base = vP + (uint32_t)(t * 16 * RS);
            ldsm4t(va, base);
            ldsm4t(vb, base + 32);
            mma16816h(o[0], eh[t], va[0], va[1]);
            mma16816h(o[1], eh[t], va[2], va[3]);
            mma16816h(o[2], eh[t], vb[0], vb[1]);
            mma16816h(o[3], eh[t], vb[2], vb[3]);
            mma16816h(o[0], el[t], va[0], va[1]);
            mma16816h(o[1], el[t], va[2], va[3]);
            mma16816h(o[2], el[t], vb[0], vb[1]);
            mma16816h(o[3], el[t], vb[2], vb[3]);
        }
    }

    // ---- normalize + store ----
    if (n1 < N_TOK) {
        float* op = out + wbase + (size_t)n1 * C_DIM + h * 32;
        #pragma unroll
        for (int j = 0; j < 4; ++j)
            *(float2*)(op + 8 * j + 2 * tig) =
                make_float2(o[j][0] * rinv1, o[j][1] * rinv1);
    }
    if (n2 < N_TOK) {
        float* op = out + wbase + (size_t)n2 * C_DIM + h * 32;
        #pragma unroll
        for (int j = 0; j < 4; ++j)
            *(float2*)(op + 8 * j + 2 * tig) =
                make_float2(o[j][2] * rinv2, o[j][3] * rinv2);
    }
}

// ---------------------------------------------------------------------------
extern "C" void kernel_launch(void* const* d_in, const int* in_sizes, int n_in,
                              void* d_out, int out_size) {
    const float* q       = (const float*)d_in[0];
    const float* k       = (const float*)d_in[1];
    const float* v       = (const float*)d_in[2];
    const float* rel_pos = (const float*)d_in[3];
    const float* w1      = (const float*)d_in[4];
    const float* b1      = (const float*)d_in[5];
    const float* w2      = (const float*)d_in[6];
    const float* b2      = (const float*)d_in[7];
    float* out = (float*)d_out;

    const int nwin = in_sizes[0] / (N_TOK * C_DIM);

    bias_kernel<<<(64 * 56 * 8 + 127) / 128, 128>>>(rel_pos, w1, b1, w2, b2);
    dim3 grid(nwin, 3);
    attn_kernel<<<grid, 128>>>(q, k, v, out);
}

// round 15
// speedup vs baseline: 1.6745x; 1.1476x over previous
#include <cuda_runtime.h>
#include <cuda_bf16.h>
#include <cuda_fp16.h>
#include <cstdint>

#define N_TOK 49
#define C_DIM 96
#define RS 80          // row stride bytes (64B data + 16B pad)
#define QHI 0
#define KHI 5120
#define VHI 10240
#define SMEM_BYTES 15360

__device__ __half g_bias4h[3 * 4 * 7 * 32 * 4];  // C-fragment-ordered, fp16

// ---------------------------------------------------------------------------
__device__ __forceinline__ uint32_t smem_u32(const void* p) {
    uint32_t a;
    asm("{ .reg .u64 t; cvta.to.shared.u64 t, %1; cvt.u32.u64 %0, t; }" : "=r"(a) : "l"(p));
    return a;
}
__device__ __forceinline__ void ldsm4(uint32_t r[4], uint32_t addr) {
    asm volatile("ldmatrix.sync.aligned.m8n8.x4.shared.b16 {%0,%1,%2,%3}, [%4];"
                 : "=r"(r[0]), "=r"(r[1]), "=r"(r[2]), "=r"(r[3]) : "r"(addr));
}
__device__ __forceinline__ void ldsm4t(uint32_t r[4], uint32_t addr) {
    asm volatile("ldmatrix.sync.aligned.m8n8.x4.trans.shared.b16 {%0,%1,%2,%3}, [%4];"
                 : "=r"(r[0]), "=r"(r[1]), "=r"(r[2]), "=r"(r[3]) : "r"(addr));
}
__device__ __forceinline__ void mma16816h(float c[4], const uint32_t a[4],
                                          uint32_t b0, uint32_t b1) {
    asm volatile(
        "mma.sync.aligned.m16n8k16.row.col.f32.f16.f16.f32 "
        "{%0,%1,%2,%3}, {%4,%5,%6,%7}, {%8,%9}, {%0,%1,%2,%3};"
        : "+f"(c[0]), "+f"(c[1]), "+f"(c[2]), "+f"(c[3])
        : "r"(a[0]), "r"(a[1]), "r"(a[2]), "r"(a[3]), "r"(b0), "r"(b1));
}
// split (x,y) into packed fp16 hi + fp16 lo (x ~= hi + lo)
__device__ __forceinline__ void cvt2h(float x, float y, uint32_t& hi, uint32_t& lo) {
    __half2 h = __floats2half2_rn(x, y);
    float hx = __low2float(h);
    float hy = __high2float(h);
    __half2 l = __floats2half2_rn(x - hx, y - hy);
    hi = *reinterpret_cast<uint32_t*>(&h);
    lo = *reinterpret_cast<uint32_t*>(&l);
}
__device__ __forceinline__ uint32_t pkh2(float x, float y) {
    __half2 h = __floats2half2_rn(x, y);
    return *reinterpret_cast<uint32_t*>(&h);
}

// ---------------------------------------------------------------------------
// Bias MLP, slice-parallel (8 lanes per position), writing DIRECTLY into the
// C-fragment-ordered fp16 table g_bias4h. -1e30 -> -inf in fp16 (mask OK).
// ---------------------------------------------------------------------------
__global__ void bias_kernel(const float* __restrict__ rel_pos,
                            const float* __restrict__ w1,
                            const float* __restrict__ b1,
                            const float* __restrict__ w2,
                            const float* __restrict__ b2) {
    int gid = blockIdx.x * blockDim.x + threadIdx.x;
    if (gid >= 64 * 56 * 8) return;
    const int s = gid & 7;          // hidden-slice index
    const int p = gid >> 3;         // position [0, 3584)
    const int n = p / 56;
    const int m = p - n * 56;

    float a0 = 0.f, a1 = 0.f, a2 = 0.f;
    const bool live = (n < N_TOK) && (m < N_TOK);
    if (live) {
        const int idx = n * N_TOK + m;
        const float r0 = rel_pos[2 * idx + 0];
        const float r1 = rel_pos[2 * idx + 1];
        const int j0 = s * 32;
        #pragma unroll 8
        for (int j = j0; j < j0 + 32; ++j) {
            float hj = fmaf(r0, __ldg(w1 + j), fmaf(r1, __ldg(w1 + 256 + j), __ldg(b1 + j)));
            hj = fmaxf(hj, 0.0f);
            a0 = fmaf(hj, __ldg(w2 + j * 3 + 0), a0);
            a1 = fmaf(hj, __ldg(w2 + j * 3 + 1), a1);
            a2 = fmaf(hj, __ldg(w2 + j * 3 + 2), a2);
        }
    }
    #pragma unroll
    for (int o = 1; o < 8; o <<= 1) {
        a0 += __shfl_xor_sync(0xffffffffu, a0, o);
        a1 += __shfl_xor_sync(0xffffffffu, a1, o);
        a2 += __shfl_xor_sync(0xffffffffu, a2, o);
    }
    if (s == 0) {
        float v0, v1, v2;
        if (m >= N_TOK)      { v0 = v1 = v2 = -1e30f; }   // -> -inf in fp16
        else if (n >= N_TOK) { v0 = v1 = v2 = 0.0f; }
        else { v0 = a0 + __ldg(b2 + 0); v1 = a1 + __ldg(b2 + 1); v2 = a2 + __ldg(b2 + 2); }
        const int w    = n >> 4;
        const int half = (n >> 3) & 1;
        const int g    = n & 7;
        const int j    = m >> 3;
        const int tig  = (m & 7) >> 1;
        const int comp = m & 1;
        const int lane4 = g * 4 + tig;
        const int fi    = half * 2 + comp;
        __half* base = g_bias4h + fi;
        base[(((0 * 4 + w) * 7 + j) * 32 + lane4) * 4] = __float2half(v0);
        base[(((1 * 4 + w) * 7 + j) * 32 + lane4) * 4] = __float2half(v1);
        base[(((2 * 4 + w) * 7 + j) * 32 + lane4) * 4] = __float2half(v2);
    }
}

// ---------------------------------------------------------------------------
// CTA = (window, head). 4 warps, warp = 16-row M-tile.
// QK: single fp16 both operands (q scaled). PV: fp16 2-term (e hi/lo in regs,
// v single fp16). Bias: fp16 fragment-ordered table as accumulator init.
// j=7 all-pad column block skipped.
// ---------------------------------------------------------------------------
__global__ __launch_bounds__(128, 6)
void attn_kernel(const float* __restrict__ q,
                 const float* __restrict__ k,
                 const float* __restrict__ v,
                 float*       __restrict__ out) {
    __shared__ __align__(16) char S[SMEM_BYTES];
    const uint32_t sb = smem_u32(S);

    const int tid  = threadIdx.x;
    const int lane = tid & 31;
    const int warp = tid >> 5;
    const int g    = lane >> 2;
    const int tig  = lane & 3;
    const int r0   = warp * 16;
    const int POFF = (lane & 7) + 8 * ((lane >> 3) & 1);
    const int CG   = lane >> 4;
    const int h    = blockIdx.y;
    const size_t wbase = (size_t)blockIdx.x * (N_TOK * C_DIM);
    const int n1 = r0 + g, n2 = n1 + 8;

    // ---- stage q (scaled), k, v as single fp16; zero pad rows 49..63 ----
    {
        const float SC = 0.17677669529663687f;  // 1/sqrt(32)
        #pragma unroll
        for (int it = 0; it < 4; ++it) {
            int i = tid + it * 128;            // 512 = 64 rows x 8 chunks
            int n = i >> 3, c = i & 7;
            uint32_t off = (uint32_t)(n * RS + c * 8);
            uint2 qh = make_uint2(0, 0), kh = qh, vh = qh;
            if (n < N_TOK) {
                size_t ga = wbase + (size_t)n * C_DIM + h * 32 + c * 4;
                float4 xq = *(const float4*)(q + ga);
                float4 xk = *(const float4*)(k + ga);
                float4 xv = *(const float4*)(v + ga);
                qh.x = pkh2(xq.x * SC, xq.y * SC);
                qh.y = pkh2(xq.z * SC, xq.w * SC);
                kh.x = pkh2(xk.x, xk.y);
                kh.y = pkh2(xk.z, xk.w);
                vh.x = pkh2(xv.x, xv.y);
                vh.y = pkh2(xv.z, xv.w);
            }
            *(uint2*)(S + QHI + off) = qh;
            *(uint2*)(S + KHI + off) = kh;
            *(uint2*)(S + VHI + off) = vh;
        }
    }

    // ---- bias -> accumulator init (fp16 fragment-ordered table) ----
    float acc[7][4];
    {
        const uint2* bt = (const uint2*)g_bias4h + ((h * 4 + warp) * 7) * 32 + lane;
        #pragma unroll
        for (int j = 0; j < 7; ++j) {
            uint2 bv = __ldg(bt + j * 32);
            float2 f01 = __half22float2(*reinterpret_cast<__half2*>(&bv.x));
            float2 f23 = __half22float2(*reinterpret_cast<__half2*>(&bv.y));
            acc[j][0] = f01.x;  acc[j][1] = f01.y;
            acc[j][2] = f23.x;  acc[j][3] = f23.y;
        }
    }
    __syncthreads();

    // ---- q A-fragments via ldmatrix (single fp16) ----
    uint32_t qh0[4], qh1[4];
    {
        const uint32_t aP = sb + QHI + (uint32_t)((r0 + POFF) * RS + CG * 16);
        ldsm4(qh0, aP);
        ldsm4(qh1, aP + 32);
    }

    // ---- QK: S[64x56] = bias + q_f16 @ k_f16^T ----
    {
        const uint32_t bP = sb + KHI + (uint32_t)((lane & 7) * RS + (lane >> 3) * 16);
        #pragma unroll
        for (int j = 0; j < 7; ++j) {
            uint32_t bh[4];
            ldsm4(bh, bP + (uint32_t)(j * 8 * RS));
            mma16816h(acc[j], qh0, bh[0], bh[1]);
            mma16816h(acc[j], qh1, bh[2], bh[3]);
        }
    }

    // ---- softmax in-place on acc (rows n1, n2; quad-local reductions) ----
    float mx1 = acc[0][0], mx2 = acc[0][2];
    #pragma unroll
    for (int j = 0; j < 7; ++j) {
        mx1 = fmaxf(mx1, fmaxf(acc[j][0], acc[j][1]));
        mx2 = fmaxf(mx2, fmaxf(acc[j][2], acc[j][3]));
    }
    mx1 = fmaxf(mx1, __shfl_xor_sync(0xffffffffu, mx1, 1));
    mx1 = fmaxf(mx1, __shfl_xor_sync(0xffffffffu, mx1, 2));
    mx2 = fmaxf(mx2, __shfl_xor_sync(0xffffffffu, mx2, 1));
    mx2 = fmaxf(mx2, __shfl_xor_sync(0xffffffffu, mx2, 2));
    float sum1 = 0.0f, sum2 = 0.0f;
    #pragma unroll
    for (int j = 0; j < 7; ++j) {
        acc[j][0] = __expf(acc[j][0] - mx1); sum1 += acc[j][0];
        acc[j][1] = __expf(acc[j][1] - mx1); sum1 += acc[j][1];
        acc[j][2] = __expf(acc[j][2] - mx2); sum2 += acc[j][2];
        acc[j][3] = __expf(acc[j][3] - mx2); sum2 += acc[j][3];
    }
    sum1 += __shfl_xor_sync(0xffffffffu, sum1, 1);
    sum1 += __shfl_xor_sync(0xffffffffu, sum1, 2);
    sum2 += __shfl_xor_sync(0xffffffffu, sum2, 1);
    sum2 += __shfl_xor_sync(0xffffffffu, sum2, 2);
    const float rinv1 = 1.0f / sum1;
    const float rinv2 = 1.0f / sum2;

    // ---- e A-fragments in registers: fp16 hi + fp16 lo (cols 56..63 -> 0) ----
    uint32_t eh[4][4], el[4][4];
    #pragma unroll
    for (int t = 0; t < 3; ++t) {
        cvt2h(acc[2*t][0],   acc[2*t][1],   eh[t][0], el[t][0]);
        cvt2h(acc[2*t][2],   acc[2*t][3],   eh[t][1], el[t][1]);
        cvt2h(acc[2*t+1][0], acc[2*t+1][1], eh[t][2], el[t][2]);
        cvt2h(acc[2*t+1][2], acc[2*t+1][3], eh[t][3], el[t][3]);
    }
    cvt2h(acc[6][0], acc[6][1], eh[3][0], el[3][0]);
    cvt2h(acc[6][2], acc[6][3], eh[3][1], el[3][1]);
    eh[3][2] = 0u; el[3][2] = 0u;
    eh[3][3] = 0u; el[3][3] = 0u;

    // ---- PV: O[64x32] = (e_hi + e_lo) @ v_f16  (fp16 2-term) ----
    float o[4][4];
    #pragma unroll
    for (int j = 0; j < 4; ++j)
        #pragma unroll
        for (int c = 0; c < 4; ++c) o[j][c] = 0.0f;

    {
        const uint32_t vP = sb + VHI + (uint32_t)(POFF * RS + CG * 16);
        #pragma unroll
        for (int t = 0; t < 4; ++t) {
            uint32_t va[4], vb[4];
            const uint32_t base = vP + (uint32_t)(t * 16 * RS);
            ldsm4t(va, base);
            ldsm4t(vb, base + 32);
            mma16816h(o[0], eh[t], va[0], va[1]);
            mma16816h(o[1], eh[t], va[2], va[3]);
            mma16816h(o[2], eh[t], vb[0], vb[1]);
            mma16816h(o[3], eh[t], vb[2], vb[3]);
            mma16816h(o[0], el[t], va[0], va[1]);
            mma16816h(o[1], el[t], va[2], va[3]);
            mma16816h(o[2], el[t], vb[0], vb[1]);
            mma16816h(o[3], el[t], vb[2], vb[3]);
        }
    }

    // ---- normalize + store ----
    if (n1 < N_TOK) {
        float* op = out + wbase + (size_t)n1 * C_DIM + h * 32;
        #pragma unroll
        for (int j = 0; j < 4; ++j)
            *(float2*)(op + 8 * j + 2 * tig) =
                make_float2(o[j][0] * rinv1, o[j][1] * rinv1);
    }
    if (n2 < N_TOK) {
        float* op = out + wbase + (size_t)n2 * C_DIM + h * 32;
        #pragma unroll
        for (int j = 0; j < 4; ++j)
            *(float2*)(op + 8 * j + 2 * tig) =
                make_float2(o[j][2] * rinv2, o[j][3] * rinv2);
    }
}

// ---------------------------------------------------------------------------
extern "C" void kernel_launch(void* const* d_in, const int* in_sizes, int n_in,
                              void* d_out, int out_size) {
    const float* q       = (const float*)d_in[0];
    const float* k       = (const float*)d_in[1];
    const float* v       = (const float*)d_in[2];
    const float* rel_pos = (const float*)d_in[3];
    const float* w1      = (const float*)d_in[4];
    const float* b1      = (const float*)d_in[5];
    const float* w2      = (const float*)d_in[6];
    const float* b2      = (const float*)d_in[7];
    float* out = (float*)d_out;

    const int nwin = in_sizes[0] / (N_TOK * C_DIM);

    bias_kernel<<<(64 * 56 * 8 + 127) / 128, 128>>>(rel_pos, w1, b1, w2, b2);
    dim3 grid(nwin, 3);
    attn_kernel<<<grid, 128>>>(q, k, v, out);
}

// round 16
// speedup vs baseline: 1.7745x; 1.0597x over previous
#include <cuda_runtime.h>
#include <cuda_bf16.h>
#include <cuda_fp16.h>
#include <cstdint>

#define N_TOK 49
#define C_DIM 96
#define RS 80          // row stride bytes (64B data + 16B pad)
#define QHI 0
#define KHI 5120
#define VHI 10240
#define SMEM_BYTES 15360

__device__ __half g_bias4h[3 * 4 * 7 * 32 * 4];  // C-fragment-ordered, fp16

// ---------------------------------------------------------------------------
__device__ __forceinline__ uint32_t smem_u32(const void* p) {
    uint32_t a;
    asm("{ .reg .u64 t; cvta.to.shared.u64 t, %1; cvt.u32.u64 %0, t; }" : "=r"(a) : "l"(p));
    return a;
}
__device__ __forceinline__ void ldsm4(uint32_t r[4], uint32_t addr) {
    asm volatile("ldmatrix.sync.aligned.m8n8.x4.shared.b16 {%0,%1,%2,%3}, [%4];"
                 : "=r"(r[0]), "=r"(r[1]), "=r"(r[2]), "=r"(r[3]) : "r"(addr));
}
__device__ __forceinline__ void ldsm4t(uint32_t r[4], uint32_t addr) {
    asm volatile("ldmatrix.sync.aligned.m8n8.x4.trans.shared.b16 {%0,%1,%2,%3}, [%4];"
                 : "=r"(r[0]), "=r"(r[1]), "=r"(r[2]), "=r"(r[3]) : "r"(addr));
}
__device__ __forceinline__ void mma16816h(float c[4], const uint32_t a[4],
                                          uint32_t b0, uint32_t b1) {
    asm volatile(
        "mma.sync.aligned.m16n8k16.row.col.f32.f16.f16.f32 "
        "{%0,%1,%2,%3}, {%4,%5,%6,%7}, {%8,%9}, {%0,%1,%2,%3};"
        : "+f"(c[0]), "+f"(c[1]), "+f"(c[2]), "+f"(c[3])
        : "r"(a[0]), "r"(a[1]), "r"(a[2]), "r"(a[3]), "r"(b0), "r"(b1));
}
__device__ __forceinline__ uint32_t pkh2(float x, float y) {
    __half2 h = __floats2half2_rn(x, y);
    return *reinterpret_cast<uint32_t*>(&h);
}

// ---------------------------------------------------------------------------
// Bias MLP, slice-parallel (8 lanes per position), writing DIRECTLY into the
// C-fragment-ordered fp16 table g_bias4h. -1e30 -> -inf in fp16 (mask OK).
// ---------------------------------------------------------------------------
__global__ void bias_kernel(const float* __restrict__ rel_pos,
                            const float* __restrict__ w1,
                            const float* __restrict__ b1,
                            const float* __restrict__ w2,
                            const float* __restrict__ b2) {
    int gid = blockIdx.x * blockDim.x + threadIdx.x;
    if (gid >= 64 * 56 * 8) return;
    const int s = gid & 7;          // hidden-slice index
    const int p = gid >> 3;         // position [0, 3584)
    const int n = p / 56;
    const int m = p - n * 56;

    float a0 = 0.f, a1 = 0.f, a2 = 0.f;
    const bool live = (n < N_TOK) && (m < N_TOK);
    if (live) {
        const int idx = n * N_TOK + m;
        const float r0 = rel_pos[2 * idx + 0];
        const float r1 = rel_pos[2 * idx + 1];
        const int j0 = s * 32;
        #pragma unroll 8
        for (int j = j0; j < j0 + 32; ++j) {
            float hj = fmaf(r0, __ldg(w1 + j), fmaf(r1, __ldg(w1 + 256 + j), __ldg(b1 + j)));
            hj = fmaxf(hj, 0.0f);
            a0 = fmaf(hj, __ldg(w2 + j * 3 + 0), a0);
            a1 = fmaf(hj, __ldg(w2 + j * 3 + 1), a1);
            a2 = fmaf(hj, __ldg(w2 + j * 3 + 2), a2);
        }
    }
    #pragma unroll
    for (int o = 1; o < 8; o <<= 1) {
        a0 += __shfl_xor_sync(0xffffffffu, a0, o);
        a1 += __shfl_xor_sync(0xffffffffu, a1, o);
        a2 += __shfl_xor_sync(0xffffffffu, a2, o);
    }
    if (s == 0) {
        float v0, v1, v2;
        if (m >= N_TOK)      { v0 = v1 = v2 = -1e30f; }   // -> -inf in fp16
        else if (n >= N_TOK) { v0 = v1 = v2 = 0.0f; }
        else { v0 = a0 + __ldg(b2 + 0); v1 = a1 + __ldg(b2 + 1); v2 = a2 + __ldg(b2 + 2); }
        const int w    = n >> 4;
        const int half = (n >> 3) & 1;
        const int g    = n & 7;
        const int j    = m >> 3;
        const int tig  = (m & 7) >> 1;
        const int comp = m & 1;
        const int lane4 = g * 4 + tig;
        const int fi    = half * 2 + comp;
        __half* base = g_bias4h + fi;
        base[(((0 * 4 + w) * 7 + j) * 32 + lane4) * 4] = __float2half(v0);
        base[(((1 * 4 + w) * 7 + j) * 32 + lane4) * 4] = __float2half(v1);
        base[(((2 * 4 + w) * 7 + j) * 32 + lane4) * 4] = __float2half(v2);
    }
}

// ---------------------------------------------------------------------------
// CTA = (window, head). 4 warps, warp = 16-row M-tile.
// QK: single fp16 both operands. PV: single fp16 both operands (e rounded).
// Bias: fp16 fragment-ordered table as accumulator init.
// j=7 all-pad column block skipped.
// ---------------------------------------------------------------------------
__global__ __launch_bounds__(128, 7)
void attn_kernel(const float* __restrict__ q,
                 const float* __restrict__ k,
                 const float* __restrict__ v,
                 float*       __restrict__ out) {
    __shared__ __align__(16) char S[SMEM_BYTES];
    const uint32_t sb = smem_u32(S);

    const int tid  = threadIdx.x;
    const int lane = tid & 31;
    const int warp = tid >> 5;
    const int g    = lane >> 2;
    const int tig  = lane & 3;
    const int r0   = warp * 16;
    const int POFF = (lane & 7) + 8 * ((lane >> 3) & 1);
    const int CG   = lane >> 4;
    const int h    = blockIdx.y;
    const size_t wbase = (size_t)blockIdx.x * (N_TOK * C_DIM);
    const int n1 = r0 + g, n2 = n1 + 8;

    // ---- stage q (scaled), k, v as single fp16; zero pad rows 49..63 ----
    {
        const float SC = 0.17677669529663687f;  // 1/sqrt(32)
        #pragma unroll
        for (int it = 0; it < 4; ++it) {
            int i = tid + it * 128;            // 512 = 64 rows x 8 chunks
            int n = i >> 3, c = i & 7;
            uint32_t off = (uint32_t)(n * RS + c * 8);
            uint2 qh = make_uint2(0, 0), kh = qh, vh = qh;
            if (n < N_TOK) {
                size_t ga = wbase + (size_t)n * C_DIM + h * 32 + c * 4;
                float4 xq = *(const float4*)(q + ga);
                float4 xk = *(const float4*)(k + ga);
                float4 xv = *(const float4*)(v + ga);
                qh.x = pkh2(xq.x * SC, xq.y * SC);
                qh.y = pkh2(xq.z * SC, xq.w * SC);
                kh.x = pkh2(xk.x, xk.y);
                kh.y = pkh2(xk.z, xk.w);
                vh.x = pkh2(xv.x, xv.y);
                vh.y = pkh2(xv.z, xv.w);
            }
            *(uint2*)(S + QHI + off) = qh;
            *(uint2*)(S + KHI + off) = kh;
            *(uint2*)(S + VHI + off) = vh;
        }
    }

    // ---- bias -> accumulator init (fp16 fragment-ordered table) ----
    float acc[7][4];
    {
        const uint2* bt = (const uint2*)g_bias4h + ((h * 4 + warp) * 7) * 32 + lane;
        #pragma unroll
        for (int j = 0; j < 7; ++j) {
            uint2 bv = __ldg(bt + j * 32);
            float2 f01 = __half22float2(*reinterpret_cast<__half2*>(&bv.x));
            float2 f23 = __half22float2(*reinterpret_cast<__half2*>(&bv.y));
            acc[j][0] = f01.x;  acc[j][1] = f01.y;
            acc[j][2] = f23.x;  acc[j][3] = f23.y;
        }
    }
    __syncthreads();

    // ---- q A-fragments via ldmatrix (single fp16) ----
    uint32_t qh0[4], qh1[4];
    {
        const uint32_t aP = sb + QHI + (uint32_t)((r0 + POFF) * RS + CG * 16);
        ldsm4(qh0, aP);
        ldsm4(qh1, aP + 32);
    }

    // ---- QK: S[64x56] = bias + q_f16 @ k_f16^T ----
    {
        const uint32_t bP = sb + KHI + (uint32_t)((lane & 7) * RS + (lane >> 3) * 16);
        #pragma unroll
        for (int j = 0; j < 7; ++j) {
            uint32_t bh[4];
            ldsm4(bh, bP + (uint32_t)(j * 8 * RS));
            mma16816h(acc[j], qh0, bh[0], bh[1]);
            mma16816h(acc[j], qh1, bh[2], bh[3]);
        }
    }

    // ---- softmax in-place on acc (rows n1, n2; quad-local reductions) ----
    float mx1 = acc[0][0], mx2 = acc[0][2];
    #pragma unroll
    for (int j = 0; j < 7; ++j) {
        mx1 = fmaxf(mx1, fmaxf(acc[j][0], acc[j][1]));
        mx2 = fmaxf(mx2, fmaxf(acc[j][2], acc[j][3]));
    }
    mx1 = fmaxf(mx1, __shfl_xor_sync(0xffffffffu, mx1, 1));
    mx1 = fmaxf(mx1, __shfl_xor_sync(0xffffffffu, mx1, 2));
    mx2 = fmaxf(mx2, __shfl_xor_sync(0xffffffffu, mx2, 1));
    mx2 = fmaxf(mx2, __shfl_xor_sync(0xffffffffu, mx2, 2));
    float sum1 = 0.0f, sum2 = 0.0f;
    #pragma unroll
    for (int j = 0; j < 7; ++j) {
        acc[j][0] = __expf(acc[j][0] - mx1); sum1 += acc[j][0];
        acc[j][1] = __expf(acc[j][1] - mx1); sum1 += acc[j][1];
        acc[j][2] = __expf(acc[j][2] - mx2); sum2 += acc[j][2];
        acc[j][3] = __expf(acc[j][3] - mx2); sum2 += acc[j][3];
    }
    sum1 += __shfl_xor_sync(0xffffffffu, sum1, 1);
    sum1 += __shfl_xor_sync(0xffffffffu, sum1, 2);
    sum2 += __shfl_xor_sync(0xffffffffu, sum2, 1);
    sum2 += __shfl_xor_sync(0xffffffffu, sum2, 2);
    const float rinv1 = 1.0f / sum1;
    const float rinv2 = 1.0f / sum2;

    // ---- e A-fragments: single fp16 (cols 56..63 -> 0) ----
    uint32_t eh[4][4];
    #pragma unroll
    for (int t = 0; t < 3; ++t) {
        eh[t][0] = pkh2(acc[2*t][0],   acc[2*t][1]);
        eh[t][1] = pkh2(acc[2*t][2],   acc[2*t][3]);
        eh[t][2] = pkh2(acc[2*t+1][0], acc[2*t+1][1]);
        eh[t][3] = pkh2(acc[2*t+1][2], acc[2*t+1][3]);
    }
    eh[3][0] = pkh2(acc[6][0], acc[6][1]);
    eh[3][1] = pkh2(acc[6][2], acc[6][3]);
    eh[3][2] = 0u;
    eh[3][3] = 0u;

    // ---- PV: O[64x32] = e_f16 @ v_f16 ----
    float o[4][4];
    #pragma unroll
    for (int j = 0; j < 4; ++j)
        #pragma unroll
        for (int c = 0; c < 4; ++c) o[j][c] = 0.0f;

    {
        const uint32_t vP = sb + VHI + (uint32_t)(POFF * RS + CG * 16);
        #pragma unroll
        for (int t = 0; t < 4; ++t) {
            uint32_t va[4], vb[4];
            const uint32_t base = vP + (uint32_t)(t * 16 * RS);
            ldsm4t(va, base);
            ldsm4t(vb, base + 32);
            mma16816h(o[0], eh[t], va[0], va[1]);
            mma16816h(o[1], eh[t], va[2], va[3]);
            mma16816h(o[2], eh[t], vb[0], vb[1]);
            mma16816h(o[3], eh[t], vb[2], vb[3]);
        }
    }

    // ---- normalize + store ----
    if (n1 < N_TOK) {
        float* op = out + wbase + (size_t)n1 * C_DIM + h * 32;
        #pragma unroll
        for (int j = 0; j < 4; ++j)
            *(float2*)(op + 8 * j + 2 * tig) =
                make_float2(o[j][0] * rinv1, o[j][1] * rinv1);
    }
    if (n2 < N_TOK) {
        float* op = out + wbase + (size_t)n2 * C_DIM + h * 32;
        #pragma unroll
        for (int j = 0; j < 4; ++j)
            *(float2*)(op + 8 * j + 2 * tig) =
                make_float2(o[j][2] * rinv2, o[j][3] * rinv2);
    }
}

// ---------------------------------------------------------------------------
extern "C" void kernel_launch(void* const* d_in, const int* in_sizes, int n_in,
                              void* d_out, int out_size) {
    const float* q       = (const float*)d_in[0];
    const float* k       = (const float*)d_in[1];
    const float* v       = (const float*)d_in[2];
    const float* rel_pos = (const float*)d_in[3];
    const float* w1      = (const float*)d_in[4];
    const float* b1      = (const float*)d_in[5];
    const float* w2      = (const float*)d_in[6];
    const float* b2      = (const float*)d_in[7];
    float* out = (float*)d_out;

    const int nwin = in_sizes[0] / (N_TOK * C_DIM);

    bias_kernel<<<(64 * 56 * 8 + 127) / 128, 128>>>(rel_pos, w1, b1, w2, b2);
    dim3 grid(nwin, 3);
    attn_kernel<<<grid, 128>>>(q, k, v, out);
}